// round 5
// baseline (speedup 1.0000x reference)
#include <cuda_runtime.h>

// out_matrix, label_matrix: [n, n, B] fp32, n=64, B=256.
// loss = 2*S_tri + B*n*n*relu(m), S_tri computed as (S_t + S_abs)/... :
//   per (r, batch): over strict upper triangle, t = m - (o_j-o_k)(l_j-l_k)
//   sum(t + |t|) = 2*sum relu(t);  sum t = 2016*m - (64*sum o*l - sum_o*sum_l)
// count = sum over (b,r) of [argmax_j out == argmax_j lab]

#define NBLOCKS 256
typedef unsigned long long ull;

__device__ float    g_ploss[NBLOCKS];
__device__ int      g_pcnt[NBLOCKS];
__device__ unsigned g_done = 0;

static __device__ __forceinline__ ull add2(ull a, ull b) {
    ull d; asm("add.rn.f32x2 %0, %1, %2;" : "=l"(d) : "l"(a), "l"(b)); return d;
}
static __device__ __forceinline__ ull fma2(ull a, ull b, ull c) {
    ull d; asm("fma.rn.f32x2 %0, %1, %2, %3;" : "=l"(d) : "l"(a), "l"(b), "l"(c)); return d;
}
static __device__ __forceinline__ float2 up2(ull v) {
    float2 r; asm("mov.b64 {%0, %1}, %2;" : "=f"(r.x), "=f"(r.y) : "l"(v)); return r;
}
static __device__ __forceinline__ ull pk2(float x, float y) {
    ull v; asm("mov.b64 %0, {%1, %2};" : "=l"(v) : "f"(x), "f"(y)); return v;
}

#define SGN  0x8000000080000000ULL
#define ABSM 0x7fffffff7fffffffULL

__global__ void __launch_bounds__(512, 2)
fused_pair_loss_kernel(const float* __restrict__ outm,
                       const float* __restrict__ labm,
                       const float* __restrict__ marginp,
                       float* __restrict__ out, int out_size)
{
    __shared__ ull   so[64 * 32];     // packed out  [j][bpair]   16 KB
    __shared__ ull   snl[64 * 32];    // packed -lab [j][bpair]   16 KB
    __shared__ ull   pd_sol[512];     // per-thread dot partials  4 KB x3
    __shared__ ull   pd_so[512];
    __shared__ ull   pd_sl[512];
    __shared__ ull   red[512];        // packed |t|+... reduce    4 KB
    __shared__ float fredf[256];
    __shared__ int   ired[256];
    __shared__ int   scnt[2];
    __shared__ int   sdone;

    const int bid  = blockIdx.x;
    const int r    = bid >> 2;              // row 0..63
    const int bc   = (bid & 3) * 64;        // batch-chunk base
    const int tid  = threadIdx.x;
    const int lane = tid & 31;
    const int w    = tid >> 5;              // warp role 0..15
    const float margin = __ldg(marginp);
    const ull m2 = pk2(margin, margin);

    // Stage row r for 64 batches (coalesced float2 loads).
    for (int idx = tid; idx < 64 * 32; idx += 512) {
        const int j = idx >> 5, p = idx & 31;
        const int g = (r * 64 + j) * 256 + bc + 2 * p;
        const float2 o = *(const float2*)(outm + g);
        const float2 l = *(const float2*)(labm + g);
        so[idx]  = pk2(o.x, o.y);
        snl[idx] = pk2(-l.x, -l.y);
    }
    __syncthreads();

    // Warp w owns rows {2w, 2w+1, 62-2w, 63-2w} (ascending for all w<=15).
    // 6 static pairs + C loop (60-4w iters x 2 pairs) + D loop (2w x 4)
    // = 126 packed pairs per warp, exactly uniform.
    const int jl = 2 * w;
    const int jh = 62 - 2 * w;

    ull ojn[4], ljp[4];   // -o_row, +l_row for the 4 owned rows
    ojn[0] = so [(jl    ) * 32 + lane] ^ SGN;
    ojn[1] = so [(jl + 1) * 32 + lane] ^ SGN;
    ojn[2] = so [(jh    ) * 32 + lane] ^ SGN;
    ojn[3] = so [(jh + 1) * 32 + lane] ^ SGN;
    ljp[0] = snl[(jl    ) * 32 + lane] ^ SGN;
    ljp[1] = snl[(jl + 1) * 32 + lane] ^ SGN;
    ljp[2] = snl[(jh    ) * 32 + lane] ^ SGN;
    ljp[3] = snl[(jh + 1) * 32 + lane] ^ SGN;

    ull acc0 = 0, acc1 = 0, acc2 = 0, acc3 = 0;

    // 6 static pairs among the owned rows (row[i1] < row[i2] always).
    #pragma unroll
    for (int i1 = 0; i1 < 4; i1++) {
        #pragma unroll
        for (int i2 = i1 + 1; i2 < 4; i2++) {
            const ull a = add2(ojn[i1], ojn[i2] ^ SGN);   // o_k - o_j
            const ull b = add2(ljp[i1], ljp[i2] ^ SGN);   // l_j - l_k
            acc0 = add2(acc0, fma2(a, b, m2) & ABSM);
        }
    }

    // Per-lane dot partials for the analytic term (4 owned rows).
    {
        ull nsol = 0, sOn = 0, sL = 0;
        #pragma unroll
        for (int i = 0; i < 4; i++) {
            nsol = fma2(ojn[i], ljp[i], nsol);   // -sum o*l
            sOn  = add2(sOn, ojn[i]);            // -sum o
            sL   = add2(sL,  ljp[i]);            // +sum l
        }
        pd_sol[tid] = nsol; pd_so[tid] = sOn; pd_sl[tid] = sL;
    }

    // C: k strictly between the blocks -> pairs with the 2 low rows.
    #pragma unroll 4
    for (int k = jl + 2; k < jh; k++) {
        const ull ok  = so [k * 32 + lane];
        const ull nlk = snl[k * 32 + lane];
        const ull t0 = fma2(add2(ok, ojn[0]), add2(ljp[0], nlk), m2);
        const ull t1 = fma2(add2(ok, ojn[1]), add2(ljp[1], nlk), m2);
        acc0 = add2(acc0, t0 & ABSM);
        acc1 = add2(acc1, t1 & ABSM);
    }

    // D: k past both blocks -> pairs with all 4 owned rows.
    #pragma unroll 2
    for (int k = jh + 2; k < 64; k++) {
        const ull ok  = so [k * 32 + lane];
        const ull nlk = snl[k * 32 + lane];
        const ull t0 = fma2(add2(ok, ojn[0]), add2(ljp[0], nlk), m2);
        const ull t1 = fma2(add2(ok, ojn[1]), add2(ljp[1], nlk), m2);
        const ull t2 = fma2(add2(ok, ojn[2]), add2(ljp[2], nlk), m2);
        const ull t3 = fma2(add2(ok, ojn[3]), add2(ljp[3], nlk), m2);
        acc0 = add2(acc0, t0 & ABSM);
        acc1 = add2(acc1, t1 & ABSM);
        acc2 = add2(acc2, t2 & ABSM);
        acc3 = add2(acc3, t3 & ABSM);
    }

    // Argmax-equality (warps 0,1; one lane per batch; snl negated -> argmin).
    if (w < 2) {
        const int bl = w * 32 + lane;
        const float* sof = (const float*)so;
        const float* snf = (const float*)snl;
        float ob = sof[bl]; int oi = 0;
        float lb = snf[bl]; int li = 0;
        for (int k = 1; k < 64; k++) {
            const float ov = sof[k * 64 + bl];
            if (ov > ob) { ob = ov; oi = k; }
            const float lv = snf[k * 64 + bl];
            if (lv < lb) { lb = lv; li = k; }
        }
        const unsigned ball = __ballot_sync(0xffffffffu, oi == li);
        if (lane == 0) scnt[w] = __popc(ball);
    }

    // Packed |t| reduction across the 16 warps (fixed order, deterministic).
    red[tid] = add2(add2(acc0, acc1), add2(acc2, acc3));
    __syncthreads();
    if (tid < 256) red[tid] = add2(red[tid], red[tid + 256]);
    __syncthreads();
    if (tid < 128) red[tid] = add2(red[tid], red[tid + 128]);
    __syncthreads();
    if (tid < 64)  red[tid] = add2(red[tid], red[tid + 64]);
    __syncthreads();

    float bl_loss = 0.f;
    if (tid < 32) {
        ull s_abs = add2(red[tid], red[tid + 32]);
        ull ns = pd_sol[tid], on = pd_so[tid], sl = pd_sl[tid];
        #pragma unroll
        for (int ww = 1; ww < 16; ww++) {
            ns = add2(ns, pd_sol[ww * 32 + tid]);
            on = add2(on, pd_so[ww * 32 + tid]);
            sl = add2(sl,  pd_sl[ww * 32 + tid]);
        }
        const ull c64   = pk2(64.f, 64.f);
        const ull m2016 = pk2(2016.f * margin, 2016.f * margin);
        ull A = fma2(c64, ns, m2016);       // 2016m - 64*sum(o*l)
        A = fma2(on ^ SGN, sl, A);          // + (sum o)(sum l)
        const float2 f = up2(add2(s_abs, A));
        float v = f.x + f.y;
        v += __shfl_down_sync(0xffffffffu, v, 16);
        v += __shfl_down_sync(0xffffffffu, v, 8);
        v += __shfl_down_sync(0xffffffffu, v, 4);
        v += __shfl_down_sync(0xffffffffu, v, 2);
        v += __shfl_down_sync(0xffffffffu, v, 1);
        bl_loss = v;
    }

    if (tid == 0) {
        g_ploss[bid] = bl_loss;
        g_pcnt[bid]  = scnt[0] + scnt[1];
        __threadfence();
        const unsigned t = atomicAdd(&g_done, 1u);
        sdone = (t == NBLOCKS - 1);
    }
    __syncthreads();
    if (!sdone) return;

    // Last block: deterministic final reduce over the 256 block partials.
    __threadfence();
    if (tid < 256) { fredf[tid] = g_ploss[tid]; ired[tid] = g_pcnt[tid]; }
    __syncthreads();
    #pragma unroll
    for (int s = 128; s > 0; s >>= 1) {
        if (tid < s) { fredf[tid] += fredf[tid + s]; ired[tid] += ired[tid + s]; }
        __syncthreads();
    }
    if (tid == 0) {
        // + diagonal: B*n*n terms of relu(margin)
        out[0] = fredf[0] + 1048576.f * fmaxf(margin, 0.f);
        if (out_size > 1) out[1] = (float)ired[0];
        g_done = 0;                // reset for next graph replay
    }
}

extern "C" void kernel_launch(void* const* d_in, const int* in_sizes, int n_in,
                              void* d_out, int out_size)
{
    const float* outm    = (const float*)d_in[0];
    const float* labm    = (const float*)d_in[1];
    const float* marginp = (const float*)d_in[2];
    (void)in_sizes; (void)n_in;

    fused_pair_loss_kernel<<<NBLOCKS, 512>>>(outm, labm, marginp,
                                             (float*)d_out, out_size);
}

// round 6
// speedup vs baseline: 1.0171x; 1.0171x over previous
#include <cuda_runtime.h>

// out_matrix, label_matrix: [n, n, B] fp32, n=64, B=256.
// loss = 2*S_tri + B*n*n*relu(m), S_tri computed as (S_t + S_abs)/... :
//   per (r, batch): over strict upper triangle, t = m - (o_j-o_k)(l_j-l_k)
//   sum(t + |t|) = 2*sum relu(t);  sum t = 2016*m - (64*sum o*l - sum_o*sum_l)
// count = sum over (b,r) of [argmax_j out == argmax_j lab]

#define NBLOCKS 256
typedef unsigned long long ull;

__device__ float    g_ploss[NBLOCKS];
__device__ int      g_pcnt[NBLOCKS];
__device__ unsigned g_done = 0;

static __device__ __forceinline__ ull add2(ull a, ull b) {
    ull d; asm("add.rn.f32x2 %0, %1, %2;" : "=l"(d) : "l"(a), "l"(b)); return d;
}
static __device__ __forceinline__ ull fma2(ull a, ull b, ull c) {
    ull d; asm("fma.rn.f32x2 %0, %1, %2, %3;" : "=l"(d) : "l"(a), "l"(b), "l"(c)); return d;
}
static __device__ __forceinline__ float2 up2(ull v) {
    float2 r; asm("mov.b64 {%0, %1}, %2;" : "=f"(r.x), "=f"(r.y) : "l"(v)); return r;
}
static __device__ __forceinline__ ull pk2(float x, float y) {
    ull v; asm("mov.b64 %0, {%1, %2};" : "=l"(v) : "f"(x), "f"(y)); return v;
}

#define SGN  0x8000000080000000ULL
#define ABSM 0x7fffffff7fffffffULL

__global__ void __launch_bounds__(512, 2)
fused_pair_loss_kernel(const float* __restrict__ outm,
                       const float* __restrict__ labm,
                       const float* __restrict__ marginp,
                       float* __restrict__ out, int out_size)
{
    __shared__ ull   so[64 * 32];     // packed out  [j][bpair]   16 KB
    __shared__ ull   snl[64 * 32];    // packed -lab [j][bpair]   16 KB
    __shared__ ull   pd_sol[512];     // per-thread dot partials  4 KB x3
    __shared__ ull   pd_so[512];
    __shared__ ull   pd_sl[512];
    __shared__ ull   red[512];        // packed |t|+... reduce    4 KB
    __shared__ float fredf[256];
    __shared__ int   ired[256];
    __shared__ int   scnt[2];
    __shared__ int   sdone;

    const int bid  = blockIdx.x;
    const int r    = bid >> 2;              // row 0..63
    const int bc   = (bid & 3) * 64;        // batch-chunk base
    const int tid  = threadIdx.x;
    const int lane = tid & 31;
    const int w    = tid >> 5;              // warp role 0..15
    const float margin = __ldg(marginp);
    const ull m2 = pk2(margin, margin);

    // Stage row r for 64 batches (coalesced float2 loads).
    for (int idx = tid; idx < 64 * 32; idx += 512) {
        const int j = idx >> 5, p = idx & 31;
        const int g = (r * 64 + j) * 256 + bc + 2 * p;
        const float2 o = *(const float2*)(outm + g);
        const float2 l = *(const float2*)(labm + g);
        so[idx]  = pk2(o.x, o.y);
        snl[idx] = pk2(-l.x, -l.y);
    }
    __syncthreads();

    // Warp w owns rows {2w, 2w+1, 62-2w, 63-2w} (ascending for all w<=15).
    // 6 static pairs + C loop (60-4w iters x 2 pairs) + D loop (2w x 4)
    // = 126 packed pairs per warp, exactly uniform.
    const int jl = 2 * w;
    const int jh = 62 - 2 * w;

    ull ojn[4], ljp[4];   // -o_row, +l_row for the 4 owned rows
    ojn[0] = so [(jl    ) * 32 + lane] ^ SGN;
    ojn[1] = so [(jl + 1) * 32 + lane] ^ SGN;
    ojn[2] = so [(jh    ) * 32 + lane] ^ SGN;
    ojn[3] = so [(jh + 1) * 32 + lane] ^ SGN;
    ljp[0] = snl[(jl    ) * 32 + lane] ^ SGN;
    ljp[1] = snl[(jl + 1) * 32 + lane] ^ SGN;
    ljp[2] = snl[(jh    ) * 32 + lane] ^ SGN;
    ljp[3] = snl[(jh + 1) * 32 + lane] ^ SGN;

    ull acc0 = 0, acc1 = 0, acc2 = 0, acc3 = 0;

    // 6 static pairs among the owned rows (row[i1] < row[i2] always).
    #pragma unroll
    for (int i1 = 0; i1 < 4; i1++) {
        #pragma unroll
        for (int i2 = i1 + 1; i2 < 4; i2++) {
            const ull a = add2(ojn[i1], ojn[i2] ^ SGN);   // o_k - o_j
            const ull b = add2(ljp[i1], ljp[i2] ^ SGN);   // l_j - l_k
            acc0 = add2(acc0, fma2(a, b, m2) & ABSM);
        }
    }

    // Per-lane dot partials for the analytic term (4 owned rows).
    {
        ull nsol = 0, sOn = 0, sL = 0;
        #pragma unroll
        for (int i = 0; i < 4; i++) {
            nsol = fma2(ojn[i], ljp[i], nsol);   // -sum o*l
            sOn  = add2(sOn, ojn[i]);            // -sum o
            sL   = add2(sL,  ljp[i]);            // +sum l
        }
        pd_sol[tid] = nsol; pd_so[tid] = sOn; pd_sl[tid] = sL;
    }

    // C: k strictly between the blocks -> pairs with the 2 low rows.
    #pragma unroll 4
    for (int k = jl + 2; k < jh; k++) {
        const ull ok  = so [k * 32 + lane];
        const ull nlk = snl[k * 32 + lane];
        const ull t0 = fma2(add2(ok, ojn[0]), add2(ljp[0], nlk), m2);
        const ull t1 = fma2(add2(ok, ojn[1]), add2(ljp[1], nlk), m2);
        acc0 = add2(acc0, t0 & ABSM);
        acc1 = add2(acc1, t1 & ABSM);
    }

    // D: k past both blocks -> pairs with all 4 owned rows.
    #pragma unroll 2
    for (int k = jh + 2; k < 64; k++) {
        const ull ok  = so [k * 32 + lane];
        const ull nlk = snl[k * 32 + lane];
        const ull t0 = fma2(add2(ok, ojn[0]), add2(ljp[0], nlk), m2);
        const ull t1 = fma2(add2(ok, ojn[1]), add2(ljp[1], nlk), m2);
        const ull t2 = fma2(add2(ok, ojn[2]), add2(ljp[2], nlk), m2);
        const ull t3 = fma2(add2(ok, ojn[3]), add2(ljp[3], nlk), m2);
        acc0 = add2(acc0, t0 & ABSM);
        acc1 = add2(acc1, t1 & ABSM);
        acc2 = add2(acc2, t2 & ABSM);
        acc3 = add2(acc3, t3 & ABSM);
    }

    // Argmax-equality (warps 0,1; one lane per batch; snl negated -> argmin).
    if (w < 2) {
        const int bl = w * 32 + lane;
        const float* sof = (const float*)so;
        const float* snf = (const float*)snl;
        float ob = sof[bl]; int oi = 0;
        float lb = snf[bl]; int li = 0;
        for (int k = 1; k < 64; k++) {
            const float ov = sof[k * 64 + bl];
            if (ov > ob) { ob = ov; oi = k; }
            const float lv = snf[k * 64 + bl];
            if (lv < lb) { lb = lv; li = k; }
        }
        const unsigned ball = __ballot_sync(0xffffffffu, oi == li);
        if (lane == 0) scnt[w] = __popc(ball);
    }

    // Packed |t| reduction across the 16 warps (fixed order, deterministic).
    red[tid] = add2(add2(acc0, acc1), add2(acc2, acc3));
    __syncthreads();
    if (tid < 256) red[tid] = add2(red[tid], red[tid + 256]);
    __syncthreads();
    if (tid < 128) red[tid] = add2(red[tid], red[tid + 128]);
    __syncthreads();
    if (tid < 64)  red[tid] = add2(red[tid], red[tid + 64]);
    __syncthreads();

    float bl_loss = 0.f;
    if (tid < 32) {
        ull s_abs = add2(red[tid], red[tid + 32]);
        ull ns = pd_sol[tid], on = pd_so[tid], sl = pd_sl[tid];
        #pragma unroll
        for (int ww = 1; ww < 16; ww++) {
            ns = add2(ns, pd_sol[ww * 32 + tid]);
            on = add2(on, pd_so[ww * 32 + tid]);
            sl = add2(sl,  pd_sl[ww * 32 + tid]);
        }
        const ull c64   = pk2(64.f, 64.f);
        const ull m2016 = pk2(2016.f * margin, 2016.f * margin);
        ull A = fma2(c64, ns, m2016);       // 2016m - 64*sum(o*l)
        A = fma2(on ^ SGN, sl, A);          // + (sum o)(sum l)
        const float2 f = up2(add2(s_abs, A));
        float v = f.x + f.y;
        v += __shfl_down_sync(0xffffffffu, v, 16);
        v += __shfl_down_sync(0xffffffffu, v, 8);
        v += __shfl_down_sync(0xffffffffu, v, 4);
        v += __shfl_down_sync(0xffffffffu, v, 2);
        v += __shfl_down_sync(0xffffffffu, v, 1);
        bl_loss = v;
    }

    if (tid == 0) {
        g_ploss[bid] = bl_loss;
        g_pcnt[bid]  = scnt[0] + scnt[1];
        __threadfence();
        const unsigned t = atomicAdd(&g_done, 1u);
        sdone = (t == NBLOCKS - 1);
    }
    __syncthreads();
    if (!sdone) return;

    // Last block: deterministic final reduce over the 256 block partials.
    __threadfence();
    if (tid < 256) { fredf[tid] = g_ploss[tid]; ired[tid] = g_pcnt[tid]; }
    __syncthreads();
    #pragma unroll
    for (int s = 128; s > 0; s >>= 1) {
        if (tid < s) { fredf[tid] += fredf[tid + s]; ired[tid] += ired[tid + s]; }
        __syncthreads();
    }
    if (tid == 0) {
        // + diagonal: B*n*n terms of relu(margin)
        out[0] = fredf[0] + 1048576.f * fmaxf(margin, 0.f);
        if (out_size > 1) out[1] = (float)ired[0];
        g_done = 0;                // reset for next graph replay
    }
}

extern "C" void kernel_launch(void* const* d_in, const int* in_sizes, int n_in,
                              void* d_out, int out_size)
{
    const float* outm    = (const float*)d_in[0];
    const float* labm    = (const float*)d_in[1];
    const float* marginp = (const float*)d_in[2];
    (void)in_sizes; (void)n_in;

    fused_pair_loss_kernel<<<NBLOCKS, 512>>>(outm, labm, marginp,
                                             (float*)d_out, out_size);
}